// round 15
// baseline (speedup 1.0000x reference)
#include <cuda_runtime.h>
#include <math.h>

// Problem constants (fixed by the dataset)
#define N_NODES 3072
#define IN_DIM  512
#define HD      512      // H*D
#define D       64
#define E_EDGES 98304
#define COL0    448      // start column of head 7 in the H*D projection
#define DEG_CAP 128      // fixed-stride adjacency slot count (Poisson(32): max~64)
#define KSPLIT  4        // split-K factor for proj

// mega grid layout (order matters for the spin-flag dependencies)
#define CS_BLOCKS   192              // colsum partials, 16 rows each
#define FILL_BLOCKS 384              // 384*256 = E exactly
#define PROJ_BLOCKS 576              // KSPLIT x 3 mats x 48 row-tiles (z-major)
#define MV_BLOCKS   16               // 32 cols each
#define CS_BASE     0
#define FILL_BASE   (CS_BASE + CS_BLOCKS)
#define PROJ_BASE   (FILL_BASE + FILL_BLOCKS)
#define MV_BASE     (PROJ_BASE + PROJ_BLOCKS)
#define MEGA_BLOCKS (MV_BASE + MV_BLOCKS)
#define N_TILES     144              // 3 mats x 48 row-tiles

// launch 2: node-pair blocks (2 nodes x 128 thr) then broadcast writers
#define NODE_PAIR_BLOCKS (N_NODES / 2)       // 1536
#define BC_BLOCKS        672                 // 672 x 512 float4 = 3072*112
#define L2_GRID          (NODE_PAIR_BLOCKS + BC_BLOCKS)

#define NB(id) asm volatile("bar.sync %0, 128;" :: "r"(id) : "memory")

// ---------------- scratch (device globals: allocation-free, zero-init) -----
__device__ float g_q7[N_NODES * D];        // raw x@Wq[:,448:512] (no bias)
__device__ float g_k7[N_NODES * D];
__device__ float g_v7[N_NODES * D];
__device__ int   g_cnt[N_NODES];           // self-cleaned by node halves
__device__ int   g_edst[N_NODES * DEG_CAP];
__device__ float g_xsump[CS_BLOCKS * IN_DIM];  // colsum partials (plain stores)
__device__ __align__(16) float g_bc[COL0]; // broadcast row: mv/N + bv  (cols 0..447)
__device__ float g_vsum7[D];               // sum_m v7[m,d] incl. bias (cols 448..511)
__device__ int   g_tile_flag[N_TILES];     // z0-slice-done flags (self-cleaned)
__device__ int   g_cs_done;                // colsum-done counter (self-cleaned)

// ---------------- K1: mega kernel (colsum + fill + proj + mv) --------------
__global__ void __launch_bounds__(256)
mega_kernel(const float* __restrict__ x,
            const int*   __restrict__ ei32,
            const float* __restrict__ Wq,
            const float* __restrict__ Wk,
            const float* __restrict__ Wv,
            const float* __restrict__ bv) {
    int bid = blockIdx.x;
    int tid = threadIdx.x;

    if (bid < FILL_BASE) {
        // ---- colsum partials: 192 blocks x 16 rows, plain stores ----------
        int r0 = bid * 16;
        float s0 = 0.f, s1 = 0.f;
#pragma unroll
        for (int r = 0; r < 16; r++) {
            s0 += x[(r0 + r) * IN_DIM + tid];
            s1 += x[(r0 + r) * IN_DIM + tid + 256];
        }
        g_xsump[bid * IN_DIM + tid]       = s0;
        g_xsump[bid * IN_DIM + tid + 256] = s1;
        __syncthreads();
        __threadfence();
        if (tid == 0) atomicAdd(&g_cs_done, 1);
    } else if (bid < PROJ_BASE) {
        // ---- edge fill with per-block dtype sniff -------------------------
        // int64 layout => odd int32 words are high halves of ids < 3072 => 0.
        // int32 layout => odd words are random node ids (P(all 0) ~ 3072^-128).
        int flag = (tid < 128) ? ei32[2 * tid + 1] : 0;
        int any  = __syncthreads_or(flag);
        int is64 = (any == 0);

        int e = (bid - FILL_BASE) * 256 + tid;       // < E exactly
        int src, dst;
        if (is64) { src = ei32[2 * e]; dst = ei32[2 * (E_EDGES + e)]; }
        else      { src = ei32[e];     dst = ei32[E_EDGES + e];       }
        int pos = atomicAdd(&g_cnt[src], 1);
        if (pos < DEG_CAP) g_edst[src * DEG_CAP + pos] = dst;
    } else if (bid < MV_BASE) {
        // ---- split-K fp32 tiled GEMM: BM=64 BN=64 BK=16, 4x4 per thread ---
        int pb   = bid - PROJ_BASE;
        int z    = pb / N_TILES;             // 0..KSPLIT-1 (z0 first in grid)
        int y    = (pb % N_TILES) / 48;      // matrix
        int rowt = pb % 48;
        const float* W; float* outp;
        if      (y == 0) { W = Wq; outp = g_q7; }
        else if (y == 1) { W = Wk; outp = g_k7; }
        else             { W = Wv; outp = g_v7; }

        __shared__ __align__(16) float xsT[16][68];  // [k][row], padded
        __shared__ __align__(16) float ws[16][64];   // [k][col]

        int tx = tid & 15;
        int ty = tid >> 4;
        int row0 = rowt * 64;
        int kbeg = z * (IN_DIM / KSPLIT);
        int kend = kbeg + (IN_DIM / KSPLIT);

        float acc[4][4] = {};

        for (int k0 = kbeg; k0 < kend; k0 += 16) {
            {
                int r  = tid >> 2;
                int kk = (tid & 3) * 4;
                float4 v = *(const float4*)&x[(row0 + r) * IN_DIM + k0 + kk];
                xsT[kk + 0][r] = v.x; xsT[kk + 1][r] = v.y;
                xsT[kk + 2][r] = v.z; xsT[kk + 3][r] = v.w;
            }
            {
                int kk = tid >> 4;
                int c4 = (tid & 15) * 4;
                *(float4*)&ws[kk][c4] =
                    *(const float4*)&W[(k0 + kk) * HD + COL0 + c4];
            }
            __syncthreads();
#pragma unroll
            for (int k = 0; k < 16; k++) {
                float4 a  = *(const float4*)&xsT[k][ty * 4];
                float4 bb = *(const float4*)&ws[k][tx * 4];
                float av[4]  = {a.x, a.y, a.z, a.w};
                float bv4[4] = {bb.x, bb.y, bb.z, bb.w};
#pragma unroll
                for (int i = 0; i < 4; i++)
#pragma unroll
                    for (int j = 0; j < 4; j++)
                        acc[i][j] += av[i] * bv4[j];
            }
            __syncthreads();
        }

        int tile = y * 48 + rowt;
        if (z == 0) {
#pragma unroll
            for (int i = 0; i < 4; i++) {
                int r = row0 + ty * 4 + i;
                float4 v4 = {acc[i][0], acc[i][1], acc[i][2], acc[i][3]};
                *(float4*)&outp[r * D + tx * 4] = v4;
            }
            __syncthreads();
            __threadfence();
            if (tid == 0) atomicExch(&g_tile_flag[tile], 1);
        } else {
            if (tid == 0) {
                while (atomicAdd(&g_tile_flag[tile], 0) == 0) { __nanosleep(64); }
            }
            __syncthreads();
#pragma unroll
            for (int i = 0; i < 4; i++) {
                int r = row0 + ty * 4 + i;
#pragma unroll
                for (int j = 0; j < 4; j++)
                    atomicAdd(&outp[r * D + tx * 4 + j], acc[i][j]);
            }
        }
    } else {
        // ---- mv: derived broadcast/vsum values for 32 output columns ------
        __shared__ float xs[IN_DIM];
        __shared__ float pp[256];
        int mb = bid - MV_BASE;              // 0..15
        if (tid == 0) {
            while (atomicAdd(&g_cs_done, 0) < CS_BLOCKS) { __nanosleep(64); }
        }
        __syncthreads();
        float s0 = 0.f, s1 = 0.f;
#pragma unroll 8
        for (int b = 0; b < CS_BLOCKS; b++) {
            s0 += g_xsump[b * IN_DIM + tid];
            s1 += g_xsump[b * IN_DIM + tid + 256];
        }
        xs[tid] = s0; xs[tid + 256] = s1;
        __syncthreads();
        int j  = mb * 32 + (tid & 31);
        int k0 = (tid >> 5) * 64;
        float p = 0.f;
#pragma unroll 8
        for (int k = 0; k < 64; k++) p += xs[k0 + k] * Wv[(k0 + k) * HD + j];
        pp[tid] = p;
        __syncthreads();
        if (tid < 32) {
            float q = 0.f;
#pragma unroll
            for (int s = 0; s < 8; s++) q += pp[tid + 32 * s];
            int jj = mb * 32 + tid;
            if (jj < COL0) g_bc[jj] = q * (1.f / N_NODES) + bv[jj];
            else           g_vsum7[jj - COL0] = q + (float)N_NODES * bv[jj];
        }
    }
}

// ---------------- K2: node-pair kernel + broadcast writers -----------------
// node-pair blocks (bid < 1536): two independent 128-thread halves, each
// running the proven R11 node pipeline on its own node, synced by named
// barriers (bar.sync 1/2, 128). z fused into Phase A via smem atomic.
// BC blocks: float4-copy the broadcast row into cols 0..447.
__global__ void __launch_bounds__(256)
node_pair_kernel(const float* __restrict__ bq,
                 const float* __restrict__ bk,
                 const float* __restrict__ bv,
                 float* __restrict__ out) {
    int tid = threadIdx.x;

    if (blockIdx.x >= NODE_PAIR_BLOCKS) {
        // ---- broadcast writer: 512 float4 per block (2 per thread) --------
        int base = (blockIdx.x - NODE_PAIR_BLOCKS) * 512;
#pragma unroll
        for (int k = 0; k < 2; k++) {
            int idx = base + k * 256 + tid;          // < 344064
            int n   = idx / (COL0 / 4);
            int c4  = idx - n * (COL0 / 4);
            float4 v = *(const float4*)&g_bc[c4 * 4];
            *(float4*)&out[n * HD + c4 * 4] = v;
        }
        return;
    }

    __shared__ __align__(16) float qs[2][64];   // q row + bq
    __shared__ __align__(16) float bks[2][64];
    __shared__ __align__(16) float bvs[2][64];
    __shared__ int   dlist[2][DEG_CAP];
    __shared__ float w[2][DEG_CAP];             // expm1 weights (0 for dups)
    __shared__ unsigned char keep[2][DEG_CAP];
    __shared__ unsigned bm[2][N_NODES / 32];    // 96-word dst bitmaps
    __shared__ float pacc[2][2][64];
    __shared__ float zs[2];
    __shared__ int   m_s[2];

    int h   = tid >> 7;              // half index 0/1
    int ht  = tid & 127;             // thread-in-half
    int bar = 1 + h;                 // named barrier id (128 threads each)
    int n   = blockIdx.x * 2 + h;

    if (ht == 0) {
        int mm = g_cnt[n];
        g_cnt[n] = 0;                // self-clean for next graph replay
        m_s[h] = (mm > DEG_CAP) ? DEG_CAP : mm;
        zs[h] = 0.f;
        if (n < N_TILES) g_tile_flag[n] = 0;
        if (n == N_TILES) g_cs_done = 0;
    }
    if (ht >= 64) {
        int c = ht - 64;
        qs[h][c]  = g_q7[n * D + c] + bq[COL0 + c];
        bks[h][c] = bk[COL0 + c];
        bvs[h][c] = bv[COL0 + c];
    }
    if (ht < N_NODES / 32) bm[h][ht] = 0u;
    NB(bar);                         // (1) prologue done for this half

    // dlist load fused with bitmap dedupe (any-survivor == .set() semantics:
    // duplicate (src,dst) edges carry identical scores)
    int m = m_s[h];
    for (int i = ht; i < m; i += 128) {
        int d = g_edst[n * DEG_CAP + i];
        dlist[h][i] = d;
        unsigned mask = 1u << (d & 31);
        unsigned old  = atomicOr(&bm[h][d >> 5], mask);
        keep[h][i] = (old & mask) ? 0 : 1;
    }
    NB(bar);                         // (2)

    // Phase A: half-warp (16 lanes) per edge, fused z accumulation
    {
        int hw = ht >> 4;            // 0..7
        int hl = ht & 15;            // 0..15
        unsigned hmask = 0xFFFFu << (((tid >> 4) & 1) * 16);
        float4 q4  = ((const float4*)qs[h])[hl];
        float4 bk4 = ((const float4*)bks[h])[hl];
        float zz = 0.f;
        for (int i = hw; i < m; i += 8) {
            int d = dlist[h][i];
            float4 k4 = ((const float4*)(g_k7 + d * D))[hl];
            float p = q4.x * (k4.x + bk4.x) + q4.y * (k4.y + bk4.y)
                    + q4.z * (k4.z + bk4.z) + q4.w * (k4.w + bk4.w);
#pragma unroll
            for (int o = 8; o; o >>= 1) p += __shfl_xor_sync(hmask, p, o);
            if (hl == 0) {
                float ww = keep[h][i] ? expm1f(p * 0.125f) : 0.f;  // e^s-1
                w[h][i] = ww;
                zz += ww;
            }
        }
        if (hl == 0 && zz != 0.f) atomicAdd(&zs[h], zz);
    }
    NB(bar);                         // (3)

    // Phase C: channel-parallel weighted-V accumulate, 2 groups x 64 ch
    {
        int c = ht & 63;
        int g = ht >> 6;             // 0 or 1
        float bvc = bvs[h][c];
        float a = 0.f;
        int i = g;
        for (; i + 8 <= m; i += 8) { // 4-deep MLP per group
            a += w[h][i]     * (g_v7[dlist[h][i]     * D + c] + bvc);
            a += w[h][i + 2] * (g_v7[dlist[h][i + 2] * D + c] + bvc);
            a += w[h][i + 4] * (g_v7[dlist[h][i + 4] * D + c] + bvc);
            a += w[h][i + 6] * (g_v7[dlist[h][i + 6] * D + c] + bvc);
        }
        for (; i < m; i += 2)
            a += w[h][i] * (g_v7[dlist[h][i] * D + c] + bvc);
        pacc[h][g][c] = a;
    }
    NB(bar);                         // (4)

    // head 7 output only (broadcast cols handled by BC blocks)
    if (ht < 64) {
        float a = pacc[h][0][ht] + pacc[h][1][ht];
        out[n * HD + COL0 + ht] =
            (g_vsum7[ht] + a) / ((float)N_NODES + zs[h]);
    }
}

// ---------------------------------------------------------------------------
extern "C" void kernel_launch(void* const* d_in, const int* in_sizes, int n_in,
                              void* d_out, int out_size) {
    const float* x    = (const float*)d_in[0];
    const int*   ei32 = (const int*)d_in[1];     // int32 OR int64 (sniffed per block)
    const float* Wq   = (const float*)d_in[2];
    const float* Wk   = (const float*)d_in[3];
    const float* Wv   = (const float*)d_in[4];
    const float* bq   = (const float*)d_in[5];
    const float* bk   = (const float*)d_in[6];
    const float* bv   = (const float*)d_in[7];
    float* out = (float*)d_out;

    mega_kernel<<<MEGA_BLOCKS, 256>>>(x, ei32, Wq, Wk, Wv, bv);
    node_pair_kernel<<<L2_GRID, 256>>>(bq, bk, bv, out);
}

// round 16
// speedup vs baseline: 1.4190x; 1.4190x over previous
#include <cuda_runtime.h>
#include <math.h>

// Problem constants (fixed by the dataset)
#define N_NODES 3072
#define IN_DIM  512
#define HD      512      // H*D
#define D       64
#define E_EDGES 98304
#define COL0    448      // start column of head 7 in the H*D projection
#define DEG_CAP 128      // fixed-stride adjacency slot count (Poisson(32): max~64)
#define KSPLIT  4        // split-K factor for proj

// mega grid layout (order matters for the spin-flag dependencies)
#define CS_BLOCKS   192              // colsum partials, 16 rows each
#define FILL_BLOCKS 384              // 384*256 = E exactly
#define PROJ_BLOCKS 576              // KSPLIT x 3 mats x 48 row-tiles (z-major)
#define MV_BLOCKS   16               // 32 cols each
#define CS_BASE     0
#define FILL_BASE   (CS_BASE + CS_BLOCKS)
#define PROJ_BASE   (FILL_BASE + FILL_BLOCKS)
#define MV_BASE     (PROJ_BASE + PROJ_BLOCKS)
#define MEGA_BLOCKS (MV_BASE + MV_BLOCKS)
#define N_TILES     144              // 3 mats x 48 row-tiles

// launch 2 (all 128-thread blocks): node + broadcast-copy + bitmap-clear
#define BMP_WORDS   (N_NODES * N_NODES / 32)   // 294912 uints = 1.125 MB
#define BC_BLOCKS   1344             // 1344 x 256 float4 = 344064 = 3072*112
#define CLR_BLOCKS  288              // 288 x 256 uint4 = 73728 = BMP_WORDS/4
#define BC_BASE2    N_NODES
#define CLR_BASE2   (BC_BASE2 + BC_BLOCKS)
#define L2_GRID     (CLR_BASE2 + CLR_BLOCKS)

// ---------------- scratch (device globals: allocation-free, zero-init) -----
__device__ float g_q7[N_NODES * D];        // raw x@Wq[:,448:512] (no bias)
__device__ float g_k7[N_NODES * D];
__device__ float g_v7[N_NODES * D];
__device__ int   g_cnt[N_NODES];           // unique-edge counts; node self-cleans
__device__ int   g_edst[N_NODES * DEG_CAP];
__device__ unsigned g_bmp[BMP_WORDS];      // fill-time dedupe bitmap (CLR-cleaned)
__device__ float g_xsump[CS_BLOCKS * IN_DIM];  // colsum partials (plain stores)
__device__ __align__(16) float g_bc[COL0]; // broadcast row: mv/N + bv  (cols 0..447)
__device__ float g_vsum7[D];               // sum_m v7[m,d] incl. bias (cols 448..511)
__device__ int   g_tile_flag[N_TILES];     // z0-slice-done flags (self-cleaned)
__device__ int   g_cs_done;                // colsum-done counter (self-cleaned)

// ---------------- K1: mega kernel (colsum + fill + proj + mv) --------------
__global__ void __launch_bounds__(256)
mega_kernel(const float* __restrict__ x,
            const int*   __restrict__ ei32,
            const float* __restrict__ Wq,
            const float* __restrict__ Wk,
            const float* __restrict__ Wv,
            const float* __restrict__ bv) {
    int bid = blockIdx.x;
    int tid = threadIdx.x;

    if (bid < FILL_BASE) {
        // ---- colsum partials: 192 blocks x 16 rows, plain stores ----------
        int r0 = bid * 16;
        float s0 = 0.f, s1 = 0.f;
#pragma unroll
        for (int r = 0; r < 16; r++) {
            s0 += x[(r0 + r) * IN_DIM + tid];
            s1 += x[(r0 + r) * IN_DIM + tid + 256];
        }
        g_xsump[bid * IN_DIM + tid]       = s0;
        g_xsump[bid * IN_DIM + tid + 256] = s1;
        __syncthreads();
        __threadfence();
        if (tid == 0) atomicAdd(&g_cs_done, 1);
    } else if (bid < PROJ_BASE) {
        // ---- edge fill + bitmap dedupe, per-block dtype sniff -------------
        // int64 layout => odd int32 words are high halves of ids < 3072 => 0.
        // int32 layout => odd words are random node ids (P(all 0) ~ 3072^-128).
        int flag = (tid < 128) ? ei32[2 * tid + 1] : 0;
        int any  = __syncthreads_or(flag);
        int is64 = (any == 0);

        int e = (bid - FILL_BASE) * 256 + tid;       // < E exactly
        int src, dst;
        if (is64) { src = ei32[2 * e]; dst = ei32[2 * (E_EDGES + e)]; }
        else      { src = ei32[e];     dst = ei32[E_EDGES + e];       }
        // dedupe now: first setter claims the slot (dups have equal scores,
        // so any single survivor reproduces the dense .set() semantics)
        unsigned bit  = (unsigned)src * N_NODES + (unsigned)dst;
        unsigned msk  = 1u << (bit & 31);
        unsigned old  = atomicOr(&g_bmp[bit >> 5], msk);
        if (!(old & msk)) {
            int pos = atomicAdd(&g_cnt[src], 1);
            if (pos < DEG_CAP) g_edst[src * DEG_CAP + pos] = dst;
        }
    } else if (bid < MV_BASE) {
        // ---- split-K fp32 tiled GEMM: BM=64 BN=64 BK=16, 4x4 per thread ---
        int pb   = bid - PROJ_BASE;
        int z    = pb / N_TILES;             // 0..KSPLIT-1 (z0 first in grid)
        int y    = (pb % N_TILES) / 48;      // matrix
        int rowt = pb % 48;
        const float* W; float* outp;
        if      (y == 0) { W = Wq; outp = g_q7; }
        else if (y == 1) { W = Wk; outp = g_k7; }
        else             { W = Wv; outp = g_v7; }

        __shared__ __align__(16) float xsT[16][68];  // [k][row], padded
        __shared__ __align__(16) float ws[16][64];   // [k][col]

        int tx = tid & 15;
        int ty = tid >> 4;
        int row0 = rowt * 64;
        int kbeg = z * (IN_DIM / KSPLIT);
        int kend = kbeg + (IN_DIM / KSPLIT);

        float acc[4][4] = {};

        for (int k0 = kbeg; k0 < kend; k0 += 16) {
            {
                int r  = tid >> 2;
                int kk = (tid & 3) * 4;
                float4 v = *(const float4*)&x[(row0 + r) * IN_DIM + k0 + kk];
                xsT[kk + 0][r] = v.x; xsT[kk + 1][r] = v.y;
                xsT[kk + 2][r] = v.z; xsT[kk + 3][r] = v.w;
            }
            {
                int kk = tid >> 4;
                int c4 = (tid & 15) * 4;
                *(float4*)&ws[kk][c4] =
                    *(const float4*)&W[(k0 + kk) * HD + COL0 + c4];
            }
            __syncthreads();
#pragma unroll
            for (int k = 0; k < 16; k++) {
                float4 a  = *(const float4*)&xsT[k][ty * 4];
                float4 bb = *(const float4*)&ws[k][tx * 4];
                float av[4]  = {a.x, a.y, a.z, a.w};
                float bv4[4] = {bb.x, bb.y, bb.z, bb.w};
#pragma unroll
                for (int i = 0; i < 4; i++)
#pragma unroll
                    for (int j = 0; j < 4; j++)
                        acc[i][j] += av[i] * bv4[j];
            }
            __syncthreads();
        }

        int tile = y * 48 + rowt;
        if (z == 0) {
#pragma unroll
            for (int i = 0; i < 4; i++) {
                int r = row0 + ty * 4 + i;
                float4 v4 = {acc[i][0], acc[i][1], acc[i][2], acc[i][3]};
                *(float4*)&outp[r * D + tx * 4] = v4;
            }
            __syncthreads();
            __threadfence();
            if (tid == 0) atomicExch(&g_tile_flag[tile], 1);
        } else {
            if (tid == 0) {
                while (atomicAdd(&g_tile_flag[tile], 0) == 0) { __nanosleep(64); }
            }
            __syncthreads();
#pragma unroll
            for (int i = 0; i < 4; i++) {
                int r = row0 + ty * 4 + i;
#pragma unroll
                for (int j = 0; j < 4; j++)
                    atomicAdd(&outp[r * D + tx * 4 + j], acc[i][j]);
            }
        }
    } else {
        // ---- mv: derived broadcast/vsum values for 32 output columns ------
        __shared__ float xs[IN_DIM];
        __shared__ float pp[256];
        int mb = bid - MV_BASE;              // 0..15
        if (tid == 0) {
            while (atomicAdd(&g_cs_done, 0) < CS_BLOCKS) { __nanosleep(64); }
        }
        __syncthreads();
        float s0 = 0.f, s1 = 0.f;
#pragma unroll 8
        for (int b = 0; b < CS_BLOCKS; b++) {
            s0 += g_xsump[b * IN_DIM + tid];
            s1 += g_xsump[b * IN_DIM + tid + 256];
        }
        xs[tid] = s0; xs[tid + 256] = s1;
        __syncthreads();
        int j  = mb * 32 + (tid & 31);
        int k0 = (tid >> 5) * 64;
        float p = 0.f;
#pragma unroll 8
        for (int k = 0; k < 64; k++) p += xs[k0 + k] * Wv[(k0 + k) * HD + j];
        pp[tid] = p;
        __syncthreads();
        if (tid < 32) {
            float q = 0.f;
#pragma unroll
            for (int s = 0; s < 8; s++) q += pp[tid + 32 * s];
            int jj = mb * 32 + tid;
            if (jj < COL0) g_bc[jj] = q * (1.f / N_NODES) + bv[jj];
            else           g_vsum7[jj - COL0] = q + (float)N_NODES * bv[jj];
        }
    }
}

// ---------------- K2: warp-autonomous node kernel + BC + CLR ---------------
// node blocks (bid < 3072): 4 warps, each owns edges i = wid, wid+4, ...
// end-to-end (gather k+v together, dot via shfl, expm1, accumulate). One
// barrier total. No dedupe here (fill already deduped).
// BC blocks: float4-copy broadcast row. CLR blocks: re-zero dedupe bitmap.
__global__ void __launch_bounds__(128)
node_kernel(const float* __restrict__ bq,
            const float* __restrict__ bk,
            const float* __restrict__ bv,
            float* __restrict__ out) {
    int tid = threadIdx.x;
    int bid = blockIdx.x;

    if (bid >= CLR_BASE2) {
        // ---- bitmap clear: 256 uint4 per block (2 per thread) -------------
        int base = (bid - CLR_BASE2) * 256;
        uint4 z = {0u, 0u, 0u, 0u};
#pragma unroll
        for (int k = 0; k < 2; k++)
            ((uint4*)g_bmp)[base + k * 128 + tid] = z;
        return;
    }
    if (bid >= BC_BASE2) {
        // ---- broadcast writer: 256 float4 per block (2 per thread) --------
        int base = (bid - BC_BASE2) * 256;
#pragma unroll
        for (int k = 0; k < 2; k++) {
            int idx = base + k * 128 + tid;          // < 344064
            int n   = idx / (COL0 / 4);
            int c4  = idx - n * (COL0 / 4);
            float4 v = *(const float4*)&g_bc[c4 * 4];
            *(float4*)&out[n * HD + c4 * 4] = v;
        }
        return;
    }

    // ---- node block: 4 autonomous warps -----------------------------------
    int n    = bid;
    int lane = tid & 31;
    int wid  = tid >> 5;

    __shared__ float pacc[4][64];
    __shared__ float wz[4];

    // per-lane row slices straight from global (L1-broadcast hot)
    float2 q2  = ((const float2*)(g_q7 + n * D))[lane];
    float2 bq2 = ((const float2*)(bq + COL0))[lane];
    q2.x += bq2.x; q2.y += bq2.y;
    float2 bk2 = ((const float2*)(bk + COL0))[lane];
    float2 bv2 = ((const float2*)(bv + COL0))[lane];

    int m = g_cnt[n];                 // broadcast load (reset after barrier)
    if (m > DEG_CAP) m = DEG_CAP;

    float2 acc = {0.f, 0.f};
    float  zz  = 0.f;
    for (int i = wid; i < m; i += 4) {
        int d = g_edst[n * DEG_CAP + i];
        float2 k2 = ((const float2*)(g_k7 + d * D))[lane];
        float2 v2 = ((const float2*)(g_v7 + d * D))[lane];  // overlaps reduce
        float p = q2.x * (k2.x + bk2.x) + q2.y * (k2.y + bk2.y);
#pragma unroll
        for (int o = 16; o; o >>= 1) p += __shfl_xor_sync(0xffffffffu, p, o);
        float w = expm1f(p * 0.125f);        // e^s - 1, s = dot/sqrt(64)
        acc.x += w * (v2.x + bv2.x);
        acc.y += w * (v2.y + bv2.y);
        zz    += w;                          // same on all lanes
    }
    pacc[wid][2 * lane]     = acc.x;
    pacc[wid][2 * lane + 1] = acc.y;
    if (lane == 0) wz[wid] = zz;
    __syncthreads();                  // the only barrier

    if (tid < 64) {
        float a = pacc[0][tid] + pacc[1][tid] + pacc[2][tid] + pacc[3][tid];
        float z = wz[0] + wz[1] + wz[2] + wz[3];
        out[n * HD + COL0 + tid] = (g_vsum7[tid] + a) / ((float)N_NODES + z);
    }
    // self-clean replay state (after barrier: all warps read g_cnt already)
    if (tid == 0) {
        g_cnt[n] = 0;
        if (n < N_TILES) g_tile_flag[n] = 0;
        if (n == N_TILES) g_cs_done = 0;
    }
}

// ---------------------------------------------------------------------------
extern "C" void kernel_launch(void* const* d_in, const int* in_sizes, int n_in,
                              void* d_out, int out_size) {
    const float* x    = (const float*)d_in[0];
    const int*   ei32 = (const int*)d_in[1];     // int32 OR int64 (sniffed per block)
    const float* Wq   = (const float*)d_in[2];
    const float* Wk   = (const float*)d_in[3];
    const float* Wv   = (const float*)d_in[4];
    const float* bq   = (const float*)d_in[5];
    const float* bk   = (const float*)d_in[6];
    const float* bv   = (const float*)d_in[7];
    float* out = (float*)d_out;

    mega_kernel<<<MEGA_BLOCKS, 256>>>(x, ei32, Wq, Wk, Wv, bv);
    node_kernel<<<L2_GRID, 128>>>(bq, bk, bv, out);
}